// round 1
// baseline (speedup 1.0000x reference)
#include <cuda_runtime.h>

#define CROP 512
#define GRID_N 8
#define NBINS 256
#define TILE 64        // CROP / GRID_N
#define SRC_W 640
#define SRC_H 640
#define NB 64          // batch

// LUT scratch: 64 batches * 8*8 tiles * 256 bins * 4B = 4 MB
__device__ float g_luts[NB * GRID_N * GRID_N * NBINS];

// ---------------------------------------------------------------------------
// Kernel 1: per-(batch, tile) histogram -> clip -> redistribute -> cumsum LUT
// One block = one tile (64x64 = 4096 pixels), 256 threads (one per bin).
// ---------------------------------------------------------------------------
__global__ void clahe_hist_lut_kernel(const float* __restrict__ x,
                                      const int* __restrict__ hflip,
                                      const int* __restrict__ vflip,
                                      const int* __restrict__ offy,
                                      const int* __restrict__ offx,
                                      const int* __restrict__ apply_clahe) {
    const int b    = blockIdx.x >> 6;     // 64 tiles per batch
    const int tile = blockIdx.x & 63;
    if (apply_clahe[b] == 0) return;      // LUT unused for this batch

    const int ty = tile >> 3;
    const int tx = tile & 7;
    const int t  = threadIdx.x;           // 0..255

    __shared__ int   hist[NBINS];
    __shared__ float red[NBINS];
    __shared__ float sc[NBINS];

    hist[t] = 0;
    __syncthreads();

    const int   hf = hflip[b];
    const int   vf = vflip[b];
    const int   oy = offy[b];
    const int   ox = offx[b];
    const float* xb = x + (size_t)b * (SRC_W * SRC_H);

    // 4096 pixels, 256 threads -> 16 pixels each; consecutive threads take
    // consecutive columns (coalesced even when hflip reverses the order).
    #pragma unroll 4
    for (int p = t; p < TILE * TILE; p += NBINS) {
        int i = ty * TILE + (p >> 6);
        int j = tx * TILE + (p & 63);
        int sh = oy + i; if (vf) sh = (SRC_H - 1) - sh;
        int sw = ox + j; if (hf) sw = (SRC_W - 1) - sw;
        float v = xb[sh * SRC_W + sw];
        int bin = (int)(v * (float)NBINS);          // trunc toward zero (v>=0)
        bin = min(max(bin, 0), NBINS - 1);
        atomicAdd(&hist[bin], 1);
    }
    __syncthreads();

    // clip_val = 0.8 * 4096 / 256 = 12.8
    const float clip_val = 12.8f;
    float h       = (float)hist[t];
    float clipped = fminf(h, clip_val);
    float e       = h - clipped;

    // block-reduce excess over 256 bins
    red[t] = e;
    __syncthreads();
    #pragma unroll
    for (int s = 128; s > 0; s >>= 1) {
        if (t < s) red[t] += red[t + s];
        __syncthreads();
    }
    float excess = red[0];
    __syncthreads();

    float c = clipped + excess * (1.0f / (float)NBINS);

    // Hillis-Steele inclusive scan over 256 bins
    sc[t] = c;
    __syncthreads();
    #pragma unroll
    for (int s = 1; s < NBINS; s <<= 1) {
        float add = (t >= s) ? sc[t - s] : 0.0f;
        __syncthreads();
        sc[t] += add;
        __syncthreads();
    }

    float lut = sc[t] * (float)(255.0 / 4096.0);    // (NBINS-1)/tp
    lut = fminf(fmaxf(lut, 0.0f), 255.0f);

    g_luts[(((b * GRID_N + ty) * GRID_N + tx) << 8) + t] = lut;
}

// ---------------------------------------------------------------------------
// Kernel 2: per-pixel flip+crop read, bilinear LUT blend (or passthrough).
// grid = (512*512/256, 64); one thread per output pixel.
// ---------------------------------------------------------------------------
__global__ void clahe_apply_kernel(const float* __restrict__ x,
                                   const int* __restrict__ hflip,
                                   const int* __restrict__ vflip,
                                   const int* __restrict__ offy,
                                   const int* __restrict__ offx,
                                   const int* __restrict__ apply_clahe,
                                   float* __restrict__ out) {
    const int b   = blockIdx.y;
    const int idx = blockIdx.x * blockDim.x + threadIdx.x;  // 0..512*512-1
    const int i   = idx >> 9;       // row in crop
    const int j   = idx & 511;      // col in crop

    int sh = offy[b] + i; if (vflip[b]) sh = (SRC_H - 1) - sh;
    int sw = offx[b] + j; if (hflip[b]) sw = (SRC_W - 1) - sw;
    float v = x[(size_t)b * (SRC_W * SRC_H) + sh * SRC_W + sw];

    float res;
    if (apply_clahe[b]) {
        int bin = (int)(v * (float)NBINS);
        bin = min(max(bin, 0), NBINS - 1);

        float tyf = ((float)i + 0.5f) * (1.0f / (float)TILE) - 0.5f;
        float txf = ((float)j + 0.5f) * (1.0f / (float)TILE) - 0.5f;
        float y0f = floorf(tyf);
        float x0f = floorf(txf);
        float fy = tyf - y0f;
        float fx = txf - x0f;

        int y0 = min(max((int)y0f,     0), GRID_N - 1);
        int y1 = min(max((int)y0f + 1, 0), GRID_N - 1);
        int x0 = min(max((int)x0f,     0), GRID_N - 1);
        int x1 = min(max((int)x0f + 1, 0), GRID_N - 1);

        const float* lb = g_luts + ((size_t)b << 14);   // b * 8*8*256
        float v00 = lb[((y0 * GRID_N + x0) << 8) + bin];
        float v01 = lb[((y0 * GRID_N + x1) << 8) + bin];
        float v10 = lb[((y1 * GRID_N + x0) << 8) + bin];
        float v11 = lb[((y1 * GRID_N + x1) << 8) + bin];

        float top = (1.0f - fx) * v00 + fx * v01;
        float bot = (1.0f - fx) * v10 + fx * v11;
        res = ((1.0f - fy) * top + fy * bot) / 255.0f;  // /(NBINS-1)
    } else {
        res = v;
    }

    out[((size_t)b << 18) + idx] = res;
}

extern "C" void kernel_launch(void* const* d_in, const int* in_sizes, int n_in,
                              void* d_out, int out_size) {
    const float* x          = (const float*)d_in[0];
    const int*   hflip      = (const int*)d_in[1];
    const int*   vflip      = (const int*)d_in[2];
    const int*   offy       = (const int*)d_in[3];
    const int*   offx       = (const int*)d_in[4];
    const int*   apply_clahe= (const int*)d_in[5];
    float*       out        = (float*)d_out;

    // Kernel 1: 64 batches * 64 tiles blocks, 256 threads
    clahe_hist_lut_kernel<<<NB * GRID_N * GRID_N, NBINS>>>(
        x, hflip, vflip, offy, offx, apply_clahe);

    // Kernel 2: one thread per output pixel
    dim3 grid2((CROP * CROP) / 256, NB);
    clahe_apply_kernel<<<grid2, 256>>>(
        x, hflip, vflip, offy, offx, apply_clahe, out);
}

// round 2
// speedup vs baseline: 1.5461x; 1.5461x over previous
#include <cuda_runtime.h>

#define CROP 512
#define GRID_N 8
#define NBINS 256
#define TILE 64        // CROP / GRID_N
#define SRC_W 640
#define SRC_H 640
#define NB 64          // batch

// LUT scratch: 64 batches * 8*8 tiles * 256 bins * 4B = 4 MB
// Stored PRE-DIVIDED by 255 (so apply kernel skips the final divide).
__device__ float g_luts[NB * GRID_N * GRID_N * NBINS];

// ---------------------------------------------------------------------------
// Kernel 1: per-(batch, tile) histogram -> clip -> redistribute -> cumsum LUT
// One block = one tile (64x64 = 4096 pixels), 256 threads (one per bin).
// ---------------------------------------------------------------------------
__global__ void clahe_hist_lut_kernel(const float* __restrict__ x,
                                      const int* __restrict__ hflip,
                                      const int* __restrict__ vflip,
                                      const int* __restrict__ offy,
                                      const int* __restrict__ offx,
                                      const int* __restrict__ apply_clahe) {
    const int b    = blockIdx.x >> 6;     // 64 tiles per batch
    const int tile = blockIdx.x & 63;
    if (apply_clahe[b] == 0) return;      // LUT unused for this batch

    const int ty = tile >> 3;
    const int tx = tile & 7;
    const int t  = threadIdx.x;           // 0..255

    __shared__ int   hist[NBINS];
    __shared__ float red[NBINS];
    __shared__ float sc[NBINS];

    hist[t] = 0;
    __syncthreads();

    const int   hf = hflip[b];
    const int   vf = vflip[b];
    const int   oy = offy[b];
    const int   ox = offx[b];
    const float* xb = x + (size_t)b * (SRC_W * SRC_H);

    #pragma unroll 4
    for (int p = t; p < TILE * TILE; p += NBINS) {
        int i = ty * TILE + (p >> 6);
        int j = tx * TILE + (p & 63);
        int sh = oy + i; if (vf) sh = (SRC_H - 1) - sh;
        int sw = ox + j; if (hf) sw = (SRC_W - 1) - sw;
        float v = xb[sh * SRC_W + sw];
        int bin = (int)(v * (float)NBINS);          // trunc toward zero (v>=0)
        bin = min(max(bin, 0), NBINS - 1);
        atomicAdd(&hist[bin], 1);
    }
    __syncthreads();

    // clip_val = 0.8 * 4096 / 256 = 12.8
    const float clip_val = 12.8f;
    float h       = (float)hist[t];
    float clipped = fminf(h, clip_val);
    float e       = h - clipped;

    // block-reduce excess over 256 bins
    red[t] = e;
    __syncthreads();
    #pragma unroll
    for (int s = 128; s > 0; s >>= 1) {
        if (t < s) red[t] += red[t + s];
        __syncthreads();
    }
    float excess = red[0];
    __syncthreads();

    float c = clipped + excess * (1.0f / (float)NBINS);

    // Hillis-Steele inclusive scan over 256 bins
    sc[t] = c;
    __syncthreads();
    #pragma unroll
    for (int s = 1; s < NBINS; s <<= 1) {
        float add = (t >= s) ? sc[t - s] : 0.0f;
        __syncthreads();
        sc[t] += add;
        __syncthreads();
    }

    // lut = clip(cumsum * 255/4096, 0, 255) / 255  ==  clip(cumsum/4096, 0, 1)
    float lut = sc[t] * (1.0f / 4096.0f);
    lut = fminf(fmaxf(lut, 0.0f), 1.0f);

    g_luts[(((b * GRID_N + ty) * GRID_N + tx) << 8) + t] = lut;
}

// ---------------------------------------------------------------------------
// Kernel 2: one block per (batch, interpolation-cell). The bilinear cell
// indices (y0,y1,x0,x1) are constant over each of 9x9 rectangular regions
// (32- or 64-wide slabs). The block's 4 LUTs (4 KB) are staged in shared
// memory interleaved as float4 {v00,v01,v10,v11}: one LDS.128 per pixel.
// ---------------------------------------------------------------------------
__global__ void clahe_apply_kernel(const float* __restrict__ x,
                                   const int* __restrict__ hflip,
                                   const int* __restrict__ vflip,
                                   const int* __restrict__ offy,
                                   const int* __restrict__ offx,
                                   const int* __restrict__ apply_clahe,
                                   float* __restrict__ out) {
    const int b    = blockIdx.y;
    const int cell = blockIdx.x;          // 0..80
    const int cy   = cell / 9;            // 0..8  (row slab)
    const int cx   = cell - cy * 9;       // 0..8  (col slab)
    const int t    = threadIdx.x;         // 0..255

    // Slab geometry: slab c covers rows [start, start+size) with
    // floor(tyf) == c-1 for every row in the slab.
    const int ystart = (cy == 0) ? 0 : cy * TILE - 32;
    const int yend   = (cy == 8) ? CROP : cy * TILE + 32;
    const int xstart = (cx == 0) ? 0 : cx * TILE - 32;
    const int xend   = (cx == 8) ? CROP : cx * TILE + 32;
    const int xsize  = xend - xstart;               // 32 or 64
    const int npix   = (yend - ystart) * xsize;
    const int xshift = (xsize == 64) ? 6 : 5;
    const int xmask  = xsize - 1;

    const bool doCl = (apply_clahe[b] != 0);

    __shared__ float4 slut[NBINS];

    if (doCl) {
        const int y0 = min(max(cy - 1, 0), GRID_N - 1);
        const int y1 = min(cy, GRID_N - 1);
        const int x0 = min(max(cx - 1, 0), GRID_N - 1);
        const int x1 = min(cx, GRID_N - 1);
        const float* lb = g_luts + ((size_t)b << 14);   // b * 64 * 256
        const float* p00 = lb + ((y0 * GRID_N + x0) << 8);
        const float* p01 = lb + ((y0 * GRID_N + x1) << 8);
        const float* p10 = lb + ((y1 * GRID_N + x0) << 8);
        const float* p11 = lb + ((y1 * GRID_N + x1) << 8);
        slut[t] = make_float4(p00[t], p01[t], p10[t], p11[t]);
        __syncthreads();
    }

    const int   hf = hflip[b];
    const int   vf = vflip[b];
    const int   oy = offy[b];
    const int   ox = offx[b];
    const float* xb  = x + (size_t)b * (SRC_W * SRC_H);
    float*       ob  = out + ((size_t)b << 18);

    // fy/fx relative to this slab: fy = tyf - (cy-1)
    const float ybase = 0.5f * (1.0f / TILE) - 0.5f - (float)(cy - 1);
    const float xbase = 0.5f * (1.0f / TILE) - 0.5f - (float)(cx - 1);

    for (int p = t; p < npix; p += 256) {
        const int li = p >> xshift;
        const int lj = p & xmask;
        const int gi = ystart + li;
        const int gj = xstart + lj;

        int sh = oy + gi; if (vf) sh = (SRC_H - 1) - sh;
        int sw = ox + gj; if (hf) sw = (SRC_W - 1) - sw;
        float v = __ldg(xb + sh * SRC_W + sw);

        float res;
        if (doCl) {
            int bin = (int)(v * (float)NBINS);
            bin = min(max(bin, 0), NBINS - 1);

            float fy = fmaf((float)gi, 1.0f / TILE, ybase);
            float fx = fmaf((float)gj, 1.0f / TILE, xbase);
            float gy = 1.0f - fy;
            float gx = 1.0f - fx;

            float4 q = slut[bin];
            float top = gx * q.x + fx * q.y;
            float bot = gx * q.z + fx * q.w;
            res = gy * top + fy * bot;
        } else {
            res = v;
        }

        ob[(gi << 9) + gj] = res;
    }
}

extern "C" void kernel_launch(void* const* d_in, const int* in_sizes, int n_in,
                              void* d_out, int out_size) {
    const float* x          = (const float*)d_in[0];
    const int*   hflip      = (const int*)d_in[1];
    const int*   vflip      = (const int*)d_in[2];
    const int*   offy       = (const int*)d_in[3];
    const int*   offx       = (const int*)d_in[4];
    const int*   apply_clahe= (const int*)d_in[5];
    float*       out        = (float*)d_out;

    // Kernel 1: 64 batches * 64 tiles blocks, 256 threads
    clahe_hist_lut_kernel<<<NB * GRID_N * GRID_N, NBINS>>>(
        x, hflip, vflip, offy, offx, apply_clahe);

    // Kernel 2: one block per (batch, interpolation cell)
    dim3 grid2(9 * 9, NB);
    clahe_apply_kernel<<<grid2, 256>>>(
        x, hflip, vflip, offy, offx, apply_clahe, out);
}

// round 3
// speedup vs baseline: 1.9149x; 1.2385x over previous
#include <cuda_runtime.h>

#define CROP 512
#define GRID_N 8
#define NBINS 256
#define TILE 64        // CROP / GRID_N
#define SRC_W 640
#define SRC_H 640
#define NB 64          // batch
#define NWARP 8        // warps per hist block

// LUT scratch: 64 batches * 8*8 tiles * 256 bins * 4B = 4 MB
// Stored PRE-DIVIDED by 255 (so apply kernel skips the final divide).
__device__ float g_luts[NB * GRID_N * GRID_N * NBINS];

// ---------------------------------------------------------------------------
// Kernel 1: per-(batch, tile) histogram -> clip -> redistribute -> cumsum LUT
// One block = one tile (64x64 = 4096 pixels), 256 threads.
// Per-warp sub-histograms kill inter-warp atomic serialization.
// ---------------------------------------------------------------------------
__global__ void clahe_hist_lut_kernel(const float* __restrict__ x,
                                      const int* __restrict__ hflip,
                                      const int* __restrict__ vflip,
                                      const int* __restrict__ offy,
                                      const int* __restrict__ offx,
                                      const int* __restrict__ apply_clahe) {
    const int b    = blockIdx.x >> 6;     // 64 tiles per batch
    const int tile = blockIdx.x & 63;
    if (apply_clahe[b] == 0) return;      // LUT unused for this batch

    const int ty = tile >> 3;
    const int tx = tile & 7;
    const int t  = threadIdx.x;           // 0..255
    const int w  = t >> 5;                // warp id

    __shared__ int   hist[NWARP][NBINS];
    __shared__ float red[NBINS];
    __shared__ float sc[NBINS];

    #pragma unroll
    for (int k = 0; k < NWARP; k++) hist[k][t & 31 | ((t >> 5) << 5)] = 0; // zero all
    // simpler, equivalent full zero:
    #pragma unroll
    for (int k = 0; k < NWARP; k++) hist[k][t] = 0;
    __syncthreads();

    const int   hf = hflip[b];
    const int   vf = vflip[b];
    const int   oy = offy[b];
    const int   ox = offx[b];
    const float* xb = x + (size_t)b * (SRC_W * SRC_H);

    #pragma unroll 4
    for (int p = t; p < TILE * TILE; p += NBINS) {
        int i = ty * TILE + (p >> 6);
        int j = tx * TILE + (p & 63);
        int sh = oy + i; if (vf) sh = (SRC_H - 1) - sh;
        int sw = ox + j; if (hf) sw = (SRC_W - 1) - sw;
        float v = xb[sh * SRC_W + sw];
        int bin = (int)(v * (float)NBINS);          // trunc toward zero (v>=0)
        bin = min(max(bin, 0), NBINS - 1);
        atomicAdd(&hist[w][bin], 1);
    }
    __syncthreads();

    // fold per-warp histograms; clip_val = 0.8 * 4096 / 256 = 12.8
    int hsum = 0;
    #pragma unroll
    for (int k = 0; k < NWARP; k++) hsum += hist[k][t];

    const float clip_val = 12.8f;
    float h       = (float)hsum;
    float clipped = fminf(h, clip_val);
    float e       = h - clipped;

    // block-reduce excess over 256 bins
    red[t] = e;
    __syncthreads();
    #pragma unroll
    for (int s = 128; s > 0; s >>= 1) {
        if (t < s) red[t] += red[t + s];
        __syncthreads();
    }
    float excess = red[0];
    __syncthreads();

    float c = clipped + excess * (1.0f / (float)NBINS);

    // Hillis-Steele inclusive scan over 256 bins
    sc[t] = c;
    __syncthreads();
    #pragma unroll
    for (int s = 1; s < NBINS; s <<= 1) {
        float add = (t >= s) ? sc[t - s] : 0.0f;
        __syncthreads();
        sc[t] += add;
        __syncthreads();
    }

    // lut = clip(cumsum * 255/4096, 0, 255) / 255  ==  clip(cumsum/4096, 0, 1)
    float lut = sc[t] * (1.0f / 4096.0f);
    lut = fminf(fmaxf(lut, 0.0f), 1.0f);

    g_luts[(((b * GRID_N + ty) * GRID_N + tx) << 8) + t] = lut;
}

// ---------------------------------------------------------------------------
// Kernel 2: one block per (batch, interpolation-cell); 4 pixels per thread
// per iteration (same row, 4 consecutive columns) with STG.128 output.
// The cell's 4 LUTs live in smem interleaved as float4 {v00,v01,v10,v11}.
// ---------------------------------------------------------------------------
__global__ void clahe_apply_kernel(const float* __restrict__ x,
                                   const int* __restrict__ hflip,
                                   const int* __restrict__ vflip,
                                   const int* __restrict__ offy,
                                   const int* __restrict__ offx,
                                   const int* __restrict__ apply_clahe,
                                   float* __restrict__ out) {
    const int b    = blockIdx.y;
    const int cell = blockIdx.x;          // 0..80
    const int cy   = cell / 9;            // 0..8  (row slab)
    const int cx   = cell - cy * 9;       // 0..8  (col slab)
    const int t    = threadIdx.x;         // 0..255

    // Slab geometry: rows in slab cy all have floor(tyf) == cy-1.
    const int ystart = (cy == 0) ? 0 : cy * TILE - 32;
    const int yend   = (cy == 8) ? CROP : cy * TILE + 32;
    const int xstart = (cx == 0) ? 0 : cx * TILE - 32;
    const int xend   = (cx == 8) ? CROP : cx * TILE + 32;
    const int xsize  = xend - xstart;               // 32 or 64
    const int ng     = ((yend - ystart) * xsize) >> 2;   // groups of 4 pixels
    const int xsh4   = (xsize == 64) ? 4 : 3;            // log2(xsize/4)
    const int xmask4 = (xsize >> 2) - 1;

    const bool doCl = (apply_clahe[b] != 0);

    __shared__ float4 slut[NBINS];

    if (doCl) {
        const int y0 = min(max(cy - 1, 0), GRID_N - 1);
        const int y1 = min(cy, GRID_N - 1);
        const int x0 = min(max(cx - 1, 0), GRID_N - 1);
        const int x1 = min(cx, GRID_N - 1);
        const float* lb = g_luts + ((size_t)b << 14);   // b * 64 * 256
        const float* p00 = lb + ((y0 * GRID_N + x0) << 8);
        const float* p01 = lb + ((y0 * GRID_N + x1) << 8);
        const float* p10 = lb + ((y1 * GRID_N + x0) << 8);
        const float* p11 = lb + ((y1 * GRID_N + x1) << 8);
        slut[t] = make_float4(p00[t], p01[t], p10[t], p11[t]);
        __syncthreads();
    }

    const int   hf = hflip[b];
    const int   vf = vflip[b];
    const int   oy = offy[b];
    const int   ox = offx[b];
    const float* xb  = x + (size_t)b * (SRC_W * SRC_H);
    float*       ob  = out + ((size_t)b << 18);

    // fy/fx relative to this slab: fy = tyf - (cy-1)
    const float ybase = 0.5f * (1.0f / TILE) - 0.5f - (float)(cy - 1);
    const float xbase = 0.5f * (1.0f / TILE) - 0.5f - (float)(cx - 1);

    for (int g = t; g < ng; g += 256) {
        const int gi = ystart + (g >> xsh4);
        const int gj = xstart + ((g & xmask4) << 2);   // 4-aligned column

        int sh = oy + gi; if (vf) sh = (SRC_H - 1) - sh;
        const float* row = xb + sh * SRC_W;

        int sw0 = ox + gj;
        int sstep = 1;
        if (hf) { sw0 = (SRC_W - 1) - sw0; sstep = -1; }

        float v0 = __ldg(row + sw0);
        float v1 = __ldg(row + sw0 + sstep);
        float v2 = __ldg(row + sw0 + 2 * sstep);
        float v3 = __ldg(row + sw0 + 3 * sstep);

        float4 r;
        if (doCl) {
            int b0 = min(max((int)(v0 * (float)NBINS), 0), NBINS - 1);
            int b1 = min(max((int)(v1 * (float)NBINS), 0), NBINS - 1);
            int b2 = min(max((int)(v2 * (float)NBINS), 0), NBINS - 1);
            int b3 = min(max((int)(v3 * (float)NBINS), 0), NBINS - 1);

            float4 q0 = slut[b0];
            float4 q1 = slut[b1];
            float4 q2 = slut[b2];
            float4 q3 = slut[b3];

            float fy = fmaf((float)gi, 1.0f / TILE, ybase);
            float gy = 1.0f - fy;
            float fx0 = fmaf((float)gj, 1.0f / TILE, xbase);
            float fx1 = fx0 + (1.0f / TILE);
            float fx2 = fx0 + (2.0f / TILE);
            float fx3 = fx0 + (3.0f / TILE);

            r.x = gy * ((1.0f - fx0) * q0.x + fx0 * q0.y) + fy * ((1.0f - fx0) * q0.z + fx0 * q0.w);
            r.y = gy * ((1.0f - fx1) * q1.x + fx1 * q1.y) + fy * ((1.0f - fx1) * q1.z + fx1 * q1.w);
            r.z = gy * ((1.0f - fx2) * q2.x + fx2 * q2.y) + fy * ((1.0f - fx2) * q2.z + fx2 * q2.w);
            r.w = gy * ((1.0f - fx3) * q3.x + fx3 * q3.y) + fy * ((1.0f - fx3) * q3.z + fx3 * q3.w);
        } else {
            r = make_float4(v0, v1, v2, v3);
        }

        *reinterpret_cast<float4*>(ob + (gi << 9) + gj) = r;
    }
}

extern "C" void kernel_launch(void* const* d_in, const int* in_sizes, int n_in,
                              void* d_out, int out_size) {
    const float* x          = (const float*)d_in[0];
    const int*   hflip      = (const int*)d_in[1];
    const int*   vflip      = (const int*)d_in[2];
    const int*   offy       = (const int*)d_in[3];
    const int*   offx       = (const int*)d_in[4];
    const int*   apply_clahe= (const int*)d_in[5];
    float*       out        = (float*)d_out;

    // Kernel 1: 64 batches * 64 tiles blocks, 256 threads
    clahe_hist_lut_kernel<<<NB * GRID_N * GRID_N, NBINS>>>(
        x, hflip, vflip, offy, offx, apply_clahe);

    // Kernel 2: one block per (batch, interpolation cell)
    dim3 grid2(9 * 9, NB);
    clahe_apply_kernel<<<grid2, 256>>>(
        x, hflip, vflip, offy, offx, apply_clahe, out);
}

// round 4
// speedup vs baseline: 1.9267x; 1.0062x over previous
#include <cuda_runtime.h>

#define CROP 512
#define GRID_N 8
#define NBINS 256
#define TILE 64        // CROP / GRID_N
#define SRC_W 640
#define SRC_H 640
#define NB 64          // batch
#define NWARP 8        // warps per hist block

// LUT scratch: 64 batches * 8*8 tiles * 256 bins * 4B = 4 MB
// Stored PRE-DIVIDED by 255 (so apply kernel skips the final divide).
__device__ float g_luts[NB * GRID_N * GRID_N * NBINS];

// ---------------------------------------------------------------------------
// Kernel 1: per-(batch, tile) histogram -> clip -> redistribute -> cumsum LUT
// One block = one tile (64x64 = 4096 pixels), 256 threads.
// Per-warp sub-histograms; shuffle-based scan (2 barriers total);
// excess derived from the scan total (no separate reduction).
// ---------------------------------------------------------------------------
__global__ void clahe_hist_lut_kernel(const float* __restrict__ x,
                                      const int* __restrict__ hflip,
                                      const int* __restrict__ vflip,
                                      const int* __restrict__ offy,
                                      const int* __restrict__ offx,
                                      const int* __restrict__ apply_clahe) {
    const int b    = blockIdx.x >> 6;     // 64 tiles per batch
    const int tile = blockIdx.x & 63;
    if (apply_clahe[b] == 0) return;      // LUT unused for this batch

    const int ty   = tile >> 3;
    const int tx   = tile & 7;
    const int t    = threadIdx.x;         // 0..255
    const int w    = t >> 5;              // warp id
    const int lane = t & 31;

    __shared__ int   hist[NWARP][NBINS];
    __shared__ float wsum[NWARP];

    #pragma unroll
    for (int k = 0; k < NWARP; k++) hist[k][t] = 0;
    __syncthreads();

    const int   hf = hflip[b];
    const int   vf = vflip[b];
    const int   oy = offy[b];
    const int   ox = offx[b];
    const float* xb = x + (size_t)b * (SRC_W * SRC_H);

    #pragma unroll 4
    for (int p = t; p < TILE * TILE; p += NBINS) {
        int i = ty * TILE + (p >> 6);
        int j = tx * TILE + (p & 63);
        int sh = oy + i; if (vf) sh = (SRC_H - 1) - sh;
        int sw = ox + j; if (hf) sw = (SRC_W - 1) - sw;
        float v = xb[sh * SRC_W + sw];
        int bin = (int)(v * (float)NBINS);          // trunc toward zero (v>=0)
        bin = min(max(bin, 0), NBINS - 1);
        atomicAdd(&hist[w][bin], 1);
    }
    __syncthreads();

    // fold per-warp histograms; clip_val = 0.8 * 4096 / 256 = 12.8
    int hsum = 0;
    #pragma unroll
    for (int k = 0; k < NWARP; k++) hsum += hist[k][t];

    float clipped = fminf((float)hsum, 12.8f);

    // inclusive scan of `clipped` over 256 threads (shuffle + 2 barriers)
    float v = clipped;
    #pragma unroll
    for (int s = 1; s < 32; s <<= 1) {
        float n = __shfl_up_sync(0xffffffffu, v, s);
        if (lane >= s) v += n;
    }
    if (lane == 31) wsum[w] = v;
    __syncthreads();
    if (w == 0 && lane < NWARP) {
        float ws = wsum[lane];
        #pragma unroll
        for (int s = 1; s < NWARP; s <<= 1) {
            float n = __shfl_up_sync(0xffu, ws, s);
            if (lane >= s) ws += n;
        }
        wsum[lane] = ws;
    }
    __syncthreads();

    float cum = v + ((w > 0) ? wsum[w - 1] : 0.0f);   // inclusive cumsum(clipped)[t]
    float total_clipped = wsum[NWARP - 1];
    float excess = 4096.0f - total_clipped;           // sum(hist) - sum(clipped)

    // cumsum(clipped + excess/256)[t] = cum + excess*(t+1)/256
    // lut = clip(cumsum * 255/4096, 0, 255) / 255  ==  clip(cumsum/4096, 0, 1)
    float lut = (cum + excess * (float)(t + 1) * (1.0f / 256.0f)) * (1.0f / 4096.0f);
    lut = fminf(fmaxf(lut, 0.0f), 1.0f);

    g_luts[(((b * GRID_N + ty) * GRID_N + tx) << 8) + t] = lut;
}

// ---------------------------------------------------------------------------
// Kernel 2: one block per (batch, interpolation-cell). Each thread owns ONE
// column (lane-contiguous => every LDG/STG is a single 128B wavefront) and
// processes 4 rows per iteration for ILP. Column-dependent terms (sw, fx, gx)
// are hoisted out of the loop. LUTs interleaved in smem as float4.
// ---------------------------------------------------------------------------
__global__ void clahe_apply_kernel(const float* __restrict__ x,
                                   const int* __restrict__ hflip,
                                   const int* __restrict__ vflip,
                                   const int* __restrict__ offy,
                                   const int* __restrict__ offx,
                                   const int* __restrict__ apply_clahe,
                                   float* __restrict__ out) {
    const int b    = blockIdx.y;
    const int cell = blockIdx.x;          // 0..80
    const int cy   = cell / 9;            // 0..8  (row slab)
    const int cx   = cell - cy * 9;       // 0..8  (col slab)
    const int t    = threadIdx.x;         // 0..255

    // Slab geometry: rows in slab cy all have floor(tyf) == cy-1.
    const int ystart = (cy == 0) ? 0 : cy * TILE - 32;
    const int yend   = (cy == 8) ? CROP : cy * TILE + 32;
    const int xstart = (cx == 0) ? 0 : cx * TILE - 32;
    const int xend   = (cx == 8) ? CROP : cx * TILE + 32;
    const int xsize  = xend - xstart;               // 32 or 64
    const int ysize  = yend - ystart;               // 32 or 64
    const int xshift = (xsize == 64) ? 6 : 5;
    const int nrg    = 256 >> xshift;               // row-groups: 4 or 8
    const int stride = nrg * 4;                     // rows consumed per iter

    const bool doCl = (apply_clahe[b] != 0);

    __shared__ float4 slut[NBINS];

    if (doCl) {
        const int y0 = min(max(cy - 1, 0), GRID_N - 1);
        const int y1 = min(cy, GRID_N - 1);
        const int x0 = min(max(cx - 1, 0), GRID_N - 1);
        const int x1 = min(cx, GRID_N - 1);
        const float* lb = g_luts + ((size_t)b << 14);   // b * 64 * 256
        const float* p00 = lb + ((y0 * GRID_N + x0) << 8);
        const float* p01 = lb + ((y0 * GRID_N + x1) << 8);
        const float* p10 = lb + ((y1 * GRID_N + x0) << 8);
        const float* p11 = lb + ((y1 * GRID_N + x1) << 8);
        slut[t] = make_float4(p00[t], p01[t], p10[t], p11[t]);
        __syncthreads();
    }

    const int   hf = hflip[b];
    const int   vf = vflip[b];
    const int   oy = offy[b];
    const int   ox = offx[b];
    const float* xb  = x + (size_t)b * (SRC_W * SRC_H);
    float*       ob  = out + ((size_t)b << 18);

    // column-dependent terms (fixed per thread)
    const int tcol = t & (xsize - 1);
    const int trow = t >> xshift;
    const int gj   = xstart + tcol;
    int sw = ox + gj; if (hf) sw = (SRC_W - 1) - sw;

    const float ybase = 0.5f * (1.0f / TILE) - 0.5f - (float)(cy - 1);
    const float xbase = 0.5f * (1.0f / TILE) - 0.5f - (float)(cx - 1);
    const float fx = fmaf((float)gj, 1.0f / TILE, xbase);
    const float gx = 1.0f - fx;

    for (int r0 = trow; r0 < ysize; r0 += stride) {
        int gi0 = ystart + r0;
        int gi1 = gi0 + nrg;
        int gi2 = gi0 + 2 * nrg;
        int gi3 = gi0 + 3 * nrg;

        int sh0 = oy + gi0; if (vf) sh0 = (SRC_H - 1) - sh0;
        int sh1 = oy + gi1; if (vf) sh1 = (SRC_H - 1) - sh1;
        int sh2 = oy + gi2; if (vf) sh2 = (SRC_H - 1) - sh2;
        int sh3 = oy + gi3; if (vf) sh3 = (SRC_H - 1) - sh3;

        float v0 = __ldg(xb + sh0 * SRC_W + sw);
        float v1 = __ldg(xb + sh1 * SRC_W + sw);
        float v2 = __ldg(xb + sh2 * SRC_W + sw);
        float v3 = __ldg(xb + sh3 * SRC_W + sw);

        float r0v, r1v, r2v, r3v;
        if (doCl) {
            int b0 = min(max((int)(v0 * (float)NBINS), 0), NBINS - 1);
            int b1 = min(max((int)(v1 * (float)NBINS), 0), NBINS - 1);
            int b2 = min(max((int)(v2 * (float)NBINS), 0), NBINS - 1);
            int b3 = min(max((int)(v3 * (float)NBINS), 0), NBINS - 1);

            float4 q0 = slut[b0];
            float4 q1 = slut[b1];
            float4 q2 = slut[b2];
            float4 q3 = slut[b3];

            float fy0 = fmaf((float)gi0, 1.0f / TILE, ybase);
            float fy1 = fy0 + (float)nrg * (1.0f / TILE);
            float fy2 = fy0 + (float)(2 * nrg) * (1.0f / TILE);
            float fy3 = fy0 + (float)(3 * nrg) * (1.0f / TILE);

            r0v = (1.0f - fy0) * (gx * q0.x + fx * q0.y) + fy0 * (gx * q0.z + fx * q0.w);
            r1v = (1.0f - fy1) * (gx * q1.x + fx * q1.y) + fy1 * (gx * q1.z + fx * q1.w);
            r2v = (1.0f - fy2) * (gx * q2.x + fx * q2.y) + fy2 * (gx * q2.z + fx * q2.w);
            r3v = (1.0f - fy3) * (gx * q3.x + fx * q3.y) + fy3 * (gx * q3.z + fx * q3.w);
        } else {
            r0v = v0; r1v = v1; r2v = v2; r3v = v3;
        }

        __stcs(ob + (gi0 << 9) + gj, r0v);
        __stcs(ob + (gi1 << 9) + gj, r1v);
        __stcs(ob + (gi2 << 9) + gj, r2v);
        __stcs(ob + (gi3 << 9) + gj, r3v);
    }
}

extern "C" void kernel_launch(void* const* d_in, const int* in_sizes, int n_in,
                              void* d_out, int out_size) {
    const float* x          = (const float*)d_in[0];
    const int*   hflip      = (const int*)d_in[1];
    const int*   vflip      = (const int*)d_in[2];
    const int*   offy       = (const int*)d_in[3];
    const int*   offx       = (const int*)d_in[4];
    const int*   apply_clahe= (const int*)d_in[5];
    float*       out        = (float*)d_out;

    // Kernel 1: 64 batches * 64 tiles blocks, 256 threads
    clahe_hist_lut_kernel<<<NB * GRID_N * GRID_N, NBINS>>>(
        x, hflip, vflip, offy, offx, apply_clahe);

    // Kernel 2: one block per (batch, interpolation cell)
    dim3 grid2(9 * 9, NB);
    clahe_apply_kernel<<<grid2, 256>>>(
        x, hflip, vflip, offy, offx, apply_clahe, out);
}

// round 5
// speedup vs baseline: 2.1619x; 1.1221x over previous
#include <cuda_runtime.h>

#define CROP 512
#define GRID_N 8
#define NBINS 256
#define TILE 64        // CROP / GRID_N
#define SRC_W 640
#define SRC_H 640
#define NB 64          // batch
#define NWARP 8        // warps per hist block

// LUT scratch: 64 batches * 8*8 tiles * 256 bins * 4B = 4 MB
// Stored PRE-DIVIDED by 255 (so apply kernel skips the final divide).
__device__ float g_luts[NB * GRID_N * GRID_N * NBINS];

// ---------------------------------------------------------------------------
// Kernel 1: per-(batch, tile) histogram -> clip -> redistribute -> cumsum LUT
// One block = one tile (64x64 = 4096 pixels), 256 threads.
// Per-warp sub-histograms; shuffle-based scan (2 barriers total).
// ---------------------------------------------------------------------------
__global__ void clahe_hist_lut_kernel(const float* __restrict__ x,
                                      const int* __restrict__ hflip,
                                      const int* __restrict__ vflip,
                                      const int* __restrict__ offy,
                                      const int* __restrict__ offx,
                                      const int* __restrict__ apply_clahe) {
    const int b    = blockIdx.x >> 6;     // 64 tiles per batch
    const int tile = blockIdx.x & 63;
    if (apply_clahe[b] == 0) return;      // LUT unused for this batch

    const int ty   = tile >> 3;
    const int tx   = tile & 7;
    const int t    = threadIdx.x;         // 0..255
    const int w    = t >> 5;              // warp id
    const int lane = t & 31;

    __shared__ int   hist[NWARP][NBINS];
    __shared__ float wsum[NWARP];

    #pragma unroll
    for (int k = 0; k < NWARP; k++) hist[k][t] = 0;
    __syncthreads();

    const int   hf = hflip[b];
    const int   vf = vflip[b];
    const int   oy = offy[b];
    const int   ox = offx[b];
    const float* xb = x + (size_t)b * (SRC_W * SRC_H);

    // signed-stride addressing (no per-pixel selects)
    const int rs = vf ? -SRC_W : SRC_W;
    const int cs = hf ? -1 : 1;
    const int rbase = (vf ? (SRC_H - 1 - oy) : oy) + ty * TILE * (vf ? -1 : 1);
    const int cbase = (hf ? (SRC_W - 1 - ox) : ox) + tx * TILE * (hf ? -1 : 1);
    const float* p0 = xb + (vf ? (SRC_H - 1 - oy) : oy) * SRC_W
                         + (hf ? (SRC_W - 1 - ox) : ox);
    (void)rbase; (void)cbase;

    #pragma unroll 4
    for (int p = t; p < TILE * TILE; p += NBINS) {
        int i = ty * TILE + (p >> 6);
        int j = tx * TILE + (p & 63);
        float v = __ldg(p0 + i * rs + j * cs);
        int bin = (int)(v * (float)NBINS);          // v in [0,1) -> 0..255
        atomicAdd(&hist[w][bin], 1);
    }
    __syncthreads();

    // fold per-warp histograms; clip_val = 0.8 * 4096 / 256 = 12.8
    int hsum = 0;
    #pragma unroll
    for (int k = 0; k < NWARP; k++) hsum += hist[k][t];

    float clipped = fminf((float)hsum, 12.8f);

    // inclusive scan of `clipped` over 256 threads (shuffle + 2 barriers)
    float v = clipped;
    #pragma unroll
    for (int s = 1; s < 32; s <<= 1) {
        float n = __shfl_up_sync(0xffffffffu, v, s);
        if (lane >= s) v += n;
    }
    if (lane == 31) wsum[w] = v;
    __syncthreads();
    if (w == 0 && lane < NWARP) {
        float ws = wsum[lane];
        #pragma unroll
        for (int s = 1; s < NWARP; s <<= 1) {
            float n = __shfl_up_sync(0xffu, ws, s);
            if (lane >= s) ws += n;
        }
        wsum[lane] = ws;
    }
    __syncthreads();

    float cum = v + ((w > 0) ? wsum[w - 1] : 0.0f);   // inclusive cumsum(clipped)[t]
    float total_clipped = wsum[NWARP - 1];
    float excess = 4096.0f - total_clipped;           // sum(hist) - sum(clipped)

    // lut = clip(cumsum(clipped + excess/256) / 4096, 0, 1)
    float lut = (cum + excess * (float)(t + 1) * (1.0f / 256.0f)) * (1.0f / 4096.0f);
    lut = fminf(fmaxf(lut, 0.0f), 1.0f);

    g_luts[(((b * GRID_N + ty) * GRID_N + tx) << 8) + t] = lut;
}

// ---------------------------------------------------------------------------
// Kernel 2: one block per (batch, interpolation-cell). Each thread owns ONE
// column (lane-contiguous 1-wavefront LDG/STG); 4 rows per iteration for ILP.
// All flip logic folded into signed row-stride pointers; output pointer and
// fy strength-reduced (exact dyadic increments). Hot loop split by doCl.
// ---------------------------------------------------------------------------
__global__ void __launch_bounds__(256, 7)
clahe_apply_kernel(const float* __restrict__ x,
                   const int* __restrict__ hflip,
                   const int* __restrict__ vflip,
                   const int* __restrict__ offy,
                   const int* __restrict__ offx,
                   const int* __restrict__ apply_clahe,
                   float* __restrict__ out) {
    const int b    = blockIdx.y;
    const int cell = blockIdx.x;          // 0..80
    const int cy   = cell / 9;            // 0..8  (row slab)
    const int cx   = cell - cy * 9;       // 0..8  (col slab)
    const int t    = threadIdx.x;         // 0..255

    // Slab geometry: rows in slab cy all have floor(tyf) == cy-1.
    const int ystart = (cy == 0) ? 0 : cy * TILE - 32;
    const int yend   = (cy == 8) ? CROP : cy * TILE + 32;
    const int xstart = (cx == 0) ? 0 : cx * TILE - 32;
    const int xend   = (cx == 8) ? CROP : cx * TILE + 32;
    const int xsize  = xend - xstart;               // 32 or 64
    const int ysize  = yend - ystart;               // 32 or 64
    const int xshift = (xsize == 64) ? 6 : 5;
    const int nrg    = 256 >> xshift;               // row-groups: 4 or 8
    const int stride = nrg * 4;                     // rows consumed per iter

    const bool doCl = (apply_clahe[b] != 0);

    __shared__ float4 slut[NBINS];

    if (doCl) {
        const int y0 = min(max(cy - 1, 0), GRID_N - 1);
        const int y1 = min(cy, GRID_N - 1);
        const int x0 = min(max(cx - 1, 0), GRID_N - 1);
        const int x1 = min(cx, GRID_N - 1);
        const float* lb = g_luts + ((size_t)b << 14);   // b * 64 * 256
        const float* p00 = lb + ((y0 * GRID_N + x0) << 8);
        const float* p01 = lb + ((y0 * GRID_N + x1) << 8);
        const float* p10 = lb + ((y1 * GRID_N + x0) << 8);
        const float* p11 = lb + ((y1 * GRID_N + x1) << 8);
        slut[t] = make_float4(p00[t], p01[t], p10[t], p11[t]);
        __syncthreads();
    }

    const int   hf = hflip[b];
    const int   vf = vflip[b];
    const int   oy = offy[b];
    const int   ox = offx[b];
    const float* xb  = x + (size_t)b * (SRC_W * SRC_H);
    float*       ob  = out + ((size_t)b << 18);

    // per-thread column / row-group mapping
    const int tcol = t & (xsize - 1);
    const int trow = t >> xshift;
    const int gj   = xstart + tcol;
    const int gi0  = ystart + trow;

    // signed-stride source addressing: addr(gi) = base + gi*rs
    const int rs = vf ? -SRC_W : SRC_W;
    const int sw = hf ? (SRC_W - 1 - ox - gj) : (ox + gj);
    const int rowbase = vf ? (SRC_H - 1 - oy) : oy;
    const float* p = xb + rowbase * SRC_W + sw + gi0 * rs;
    const int o1 = nrg * rs, o2 = 2 * nrg * rs, o3 = 3 * nrg * rs;
    const int pstep = stride * rs;

    float* q = ob + (gi0 << 9) + gj;
    const int qo = nrg << 9;
    const int qstep = stride << 9;

    const int niter = ysize / stride;     // 1, 2 or 4

    if (doCl) {
        const float ybase = 0.5f * (1.0f / TILE) - 0.5f - (float)(cy - 1);
        const float xbase = 0.5f * (1.0f / TILE) - 0.5f - (float)(cx - 1);
        const float fx  = fmaf((float)gj, 1.0f / TILE, xbase);
        float       fy  = fmaf((float)gi0, 1.0f / TILE, ybase);
        const float dfy = (float)nrg * (1.0f / TILE);       // exact dyadic
        const float sfy = (float)stride * (1.0f / TILE);    // exact dyadic

        for (int it = 0; it < niter; it++) {
            float v0 = __ldg(p);
            float v1 = __ldg(p + o1);
            float v2 = __ldg(p + o2);
            float v3 = __ldg(p + o3);

            int b0 = (int)(v0 * (float)NBINS);
            int b1 = (int)(v1 * (float)NBINS);
            int b2 = (int)(v2 * (float)NBINS);
            int b3 = (int)(v3 * (float)NBINS);

            float4 q0 = slut[b0];
            float4 q1 = slut[b1];
            float4 q2 = slut[b2];
            float4 q3 = slut[b3];

            float fy0 = fy;
            float fy1 = fy + dfy;
            float fy2 = fy + 2.0f * dfy;
            float fy3 = fy + 3.0f * dfy;

            // lerp form: top = v00 + fx*(v01-v00); res = top + fy*(bot-top)
            float t0 = fmaf(fx, q0.y - q0.x, q0.x);
            float b0f = fmaf(fx, q0.w - q0.z, q0.z);
            float t1 = fmaf(fx, q1.y - q1.x, q1.x);
            float b1f = fmaf(fx, q1.w - q1.z, q1.z);
            float t2 = fmaf(fx, q2.y - q2.x, q2.x);
            float b2f = fmaf(fx, q2.w - q2.z, q2.z);
            float t3 = fmaf(fx, q3.y - q3.x, q3.x);
            float b3f = fmaf(fx, q3.w - q3.z, q3.z);

            __stcs(q,          fmaf(fy0, b0f - t0, t0));
            __stcs(q + qo,     fmaf(fy1, b1f - t1, t1));
            __stcs(q + 2 * qo, fmaf(fy2, b2f - t2, t2));
            __stcs(q + 3 * qo, fmaf(fy3, b3f - t3, t3));

            p += pstep; q += qstep; fy += sfy;
        }
    } else {
        for (int it = 0; it < niter; it++) {
            float v0 = __ldg(p);
            float v1 = __ldg(p + o1);
            float v2 = __ldg(p + o2);
            float v3 = __ldg(p + o3);
            __stcs(q,          v0);
            __stcs(q + qo,     v1);
            __stcs(q + 2 * qo, v2);
            __stcs(q + 3 * qo, v3);
            p += pstep; q += qstep;
        }
    }
}

extern "C" void kernel_launch(void* const* d_in, const int* in_sizes, int n_in,
                              void* d_out, int out_size) {
    const float* x          = (const float*)d_in[0];
    const int*   hflip      = (const int*)d_in[1];
    const int*   vflip      = (const int*)d_in[2];
    const int*   offy       = (const int*)d_in[3];
    const int*   offx       = (const int*)d_in[4];
    const int*   apply_clahe= (const int*)d_in[5];
    float*       out        = (float*)d_out;

    // Kernel 1: 64 batches * 64 tiles blocks, 256 threads
    clahe_hist_lut_kernel<<<NB * GRID_N * GRID_N, NBINS>>>(
        x, hflip, vflip, offy, offx, apply_clahe);

    // Kernel 2: one block per (batch, interpolation cell)
    dim3 grid2(9 * 9, NB);
    clahe_apply_kernel<<<grid2, 256>>>(
        x, hflip, vflip, offy, offx, apply_clahe, out);
}